// round 13
// baseline (speedup 1.0000x reference)
#include <cuda_runtime.h>
#include <cstdint>

#define NCOLS 2048
#define ORDER 8
#define NB    296
#define TPB   256
#define TILE  6
#define NT    5    // covers up to 30 rows; blocks have 27 or 28

typedef unsigned long long ull;

__device__ __forceinline__ ull pack2(float lo, float hi) {
    ull r; asm("mov.b64 %0, {%1, %2};" : "=l"(r) : "f"(lo), "f"(hi)); return r;
}
__device__ __forceinline__ float2 unpack2(ull v) {
    float2 f; asm("mov.b64 {%0, %1}, %2;" : "=f"(f.x), "=f"(f.y) : "l"(v)); return f;
}
__device__ __forceinline__ ull ffma2(ull a, ull b, ull c) {
    ull d; asm("fma.rn.f32x2 %0, %1, %2, %3;" : "=l"(d) : "l"(a), "l"(b), "l"(c)); return d;
}
__device__ __forceinline__ ull fmul2(ull a, ull b) {
    ull d; asm("mul.rn.f32x2 %0, %1, %2;" : "=l"(d) : "l"(a), "l"(b)); return d;
}
__device__ __forceinline__ uint32_t s2u(const void* p) {
    uint32_t a;
    asm("{ .reg .u64 t; cvta.to.shared.u64 t, %1; cvt.u32.u64 %0, t; }"
        : "=r"(a) : "l"(p));
    return a;
}
__device__ __forceinline__ void cp16(uint32_t dst, const float* src) {
    asm volatile("cp.async.cg.shared.global [%0], [%1], 16;" :: "r"(dst), "l"(src));
}
__device__ __forceinline__ void cp_commit() { asm volatile("cp.async.commit_group;"); }
__device__ __forceinline__ void cp_wait0()  { asm volatile("cp.async.wait_group 0;"); }

// dynamic smem: xbuf[2][TILE][NCOLS] = 98304 bytes per block
extern __shared__ float xbuf[];

__global__ void __launch_bounds__(TPB, 2) orth_pipe(
    const float* __restrict__ x, const float* __restrict__ v,
    const float* __restrict__ d, const float* __restrict__ bias,
    float* __restrict__ y)
{
    __shared__ float gpart[8 * 36];
    __shared__ float Tneg[64];
    __shared__ float asum[8 * 49];         // [warp][row(6)*8+k], stride 49
    __shared__ float B2[TILE * 8 * 2];     // duplicated (b,b) per (row,k)

    const int t = threadIdx.x, lane = t & 31, w = t >> 5;  // 8 warps
    const int colA = t * 4;                 // cols [0,1024) slice
    const int colB = colA + 1024;           // cols [1024,2048) slice

    const int bid = blockIdx.x;
    const int nr = (bid < 200) ? 28 : 27;
    const int r0 = (bid < 200) ? bid * 28 : 200 * 28 + (bid - 200) * 27;

    // ---- kick off prefetch of tile 0 immediately ----
    const uint32_t xb_base = s2u(xbuf);
#pragma unroll
    for (int j = 0; j < TILE; ++j) {
        const int rc = (j < nr) ? j : (nr - 1);
        cp16(xb_base + (uint32_t)(j * NCOLS + colA) * 4,
             x + (size_t)(r0 + rc) * NCOLS + colA);
        cp16(xb_base + (uint32_t)(j * NCOLS + colB) * 4,
             x + (size_t)(r0 + rc) * NCOLS + colB);
    }
    cp_commit();

    // ---- V slice: 8 cols/thread, packed ----
    ull VA0[ORDER], VA1[ORDER], VB0[ORDER], VB1[ORDER];
#pragma unroll
    for (int k = 0; k < ORDER; ++k) {
        const float4 a = *reinterpret_cast<const float4*>(v + k * NCOLS + colA);
        const float4 b = *reinterpret_cast<const float4*>(v + k * NCOLS + colB);
        VA0[k] = pack2(a.x, a.y); VA1[k] = pack2(a.z, a.w);
        VB0[k] = pack2(b.x, b.y); VB1[k] = pack2(b.z, b.w);
    }

    // ================= Prologue: Gram -> Tneg =================
    {
        int idx = 0;
#pragma unroll
        for (int i = 0; i < ORDER; ++i) {
#pragma unroll
            for (int k = i; k < ORDER; ++k) {
                ull g2 = fmul2(VA0[i], VA0[k]);
                g2 = ffma2(VA1[i], VA1[k], g2);
                g2 = ffma2(VB0[i], VB0[k], g2);
                g2 = ffma2(VB1[i], VB1[k], g2);
                const float2 f = unpack2(g2);
                float gg = f.x + f.y;
#pragma unroll
                for (int m = 16; m >= 1; m >>= 1)
                    gg += __shfl_xor_sync(0xffffffffu, gg, m);
                if (lane == 0) gpart[w * 36 + idx] = gg;
                ++idx;
            }
        }
    }
    __syncthreads();
    if (t < 36) {
        float s = 0.f;
#pragma unroll
        for (int ww = 0; ww < 8; ++ww) s += gpart[ww * 36 + t];
        gpart[t] = s;
    }
    __syncthreads();
    if (t == 0) {
        float Gs[ORDER][ORDER];
        int id2 = 0;
        for (int i = 0; i < ORDER; ++i)
            for (int k = i; k < ORDER; ++k) {
                Gs[i][k] = gpart[id2]; Gs[k][i] = gpart[id2]; ++id2;
            }
        float rn[ORDER];
        for (int i = 0; i < ORDER; ++i) rn[i] = 1.0f / sqrtf(Gs[i][i]);
        float T[ORDER][ORDER];
        for (int i = 0; i < ORDER; ++i)
            for (int k = 0; k < ORDER; ++k) T[i][k] = 0.f;
        for (int i = 0; i < ORDER; ++i) T[i][i] = 2.f;
        for (int c = 1; c < ORDER; ++c)
            for (int r = 0; r < c; ++r) {
                float s = 0.f;
                for (int m = r; m < c; ++m)
                    s += T[r][m] * (Gs[m][c] * rn[m] * rn[c]);
                T[r][c] = -2.f * s;
            }
        for (int i = 0; i < ORDER; ++i)
            for (int k = 0; k < ORDER; ++k)
                Tneg[i * 8 + k] = -(rn[i] * T[i][k] * rn[k]);
    }
    __syncthreads();

    const float4 da = *reinterpret_cast<const float4*>(d + colA);
    const float4 db = *reinterpret_cast<const float4*>(d + colB);
    const float4 ba = *reinterpret_cast<const float4*>(bias + colA);
    const float4 bbv = *reinterpret_cast<const float4*>(bias + colB);
    const ull dA0 = pack2(da.x, da.y), dA1 = pack2(da.z, da.w);
    const ull dB0 = pack2(db.x, db.y), dB1 = pack2(db.z, db.w);
    const ull bA0 = pack2(ba.x, ba.y), bA1 = pack2(ba.z, ba.w);
    const ull bB0 = pack2(bbv.x, bbv.y), bB1 = pack2(bbv.z, bbv.w);

    // ================= Pipelined main loop =================
#pragma unroll 1
    for (int tt = 0; tt < NT; ++tt) {
        const int buf = tt & 1;

        cp_wait0();
        __syncthreads();               // tile tt visible; prev pass C done

        if (tt + 1 < NT) {
#pragma unroll
            for (int j = 0; j < TILE; ++j) {
                const int jr = (tt + 1) * TILE + j;
                const int rc = (jr < nr) ? jr : (nr - 1);
                cp16(xb_base + (uint32_t)(((1 - buf) * TILE + j) * NCOLS + colA) * 4,
                     x + (size_t)(r0 + rc) * NCOLS + colA);
                cp16(xb_base + (uint32_t)(((1 - buf) * TILE + j) * NCOLS + colB) * 4,
                     x + (size_t)(r0 + rc) * NCOLS + colB);
            }
            cp_commit();
        }

        const float* xs = &xbuf[buf * TILE * NCOLS];

        // ---- pass A: 8 warps per row, 6 rows ----
#pragma unroll
        for (int j = 0; j < TILE; ++j) {
            const float4 xa = *reinterpret_cast<const float4*>(xs + j * NCOLS + colA);
            const float4 xb = *reinterpret_cast<const float4*>(xs + j * NCOLS + colB);
            const ull x01 = pack2(xa.x, xa.y), x23 = pack2(xa.z, xa.w);
            const ull x45 = pack2(xb.x, xb.y), x67 = pack2(xb.z, xb.w);
            float p[8];
#pragma unroll
            for (int k = 0; k < 8; ++k) {
                ull s2 = fmul2(x01, VA0[k]);
                s2 = ffma2(x23, VA1[k], s2);
                s2 = ffma2(x45, VB0[k], s2);
                s2 = ffma2(x67, VB1[k], s2);
                const float2 f = unpack2(s2);
                p[k] = f.x + f.y;
            }
            // folded butterfly: 23 shfl; lanes 0..7 end with total for k=lane
#pragma unroll
            for (int k = 0; k < 8; ++k) {
                p[k] += __shfl_xor_sync(0xffffffffu, p[k], 16);
                p[k] += __shfl_xor_sync(0xffffffffu, p[k], 8);
            }
            const bool h4 = (lane & 4) != 0;
            float q[4];
#pragma unroll
            for (int jj = 0; jj < 4; ++jj) {
                float keep = h4 ? p[jj + 4] : p[jj];
                float send = h4 ? p[jj] : p[jj + 4];
                q[jj] = keep + __shfl_xor_sync(0xffffffffu, send, 4);
            }
            const bool h2 = (lane & 2) != 0;
            float r2[2];
#pragma unroll
            for (int jj = 0; jj < 2; ++jj) {
                float keep = h2 ? q[jj + 2] : q[jj];
                float send = h2 ? q[jj] : q[jj + 2];
                r2[jj] = keep + __shfl_xor_sync(0xffffffffu, send, 2);
            }
            const bool h1 = (lane & 1) != 0;
            float keep = h1 ? r2[1] : r2[0];
            float send = h1 ? r2[0] : r2[1];
            const float s = keep + __shfl_xor_sync(0xffffffffu, send, 1);
            if (lane < 8) asum[w * 49 + j * 8 + lane] = s;
        }
        __syncthreads();

        // ---- pass B: 64 threads (2 full warps); collapse 8 warps + T' ----
        if (t < 64) {
            const int row = t >> 3, k = t & 7;          // rows 0..7
            const int rowc = (row < TILE) ? row : (TILE - 1);
            float a = 0.f;
#pragma unroll
            for (int ww = 0; ww < 8; ++ww)
                a += asum[ww * 49 + rowc * 8 + k];
            float bk = 0.f;
#pragma unroll
            for (int i = 0; i < 8; ++i) {
                const float ai = __shfl_sync(0xffffffffu, a, (lane & 24) | i);
                bk = fmaf(ai, Tneg[i * 8 + k], bk);
            }
            if (row < TILE) {
                const int o = (row * 8 + k) * 2;
                B2[o] = bk; B2[o + 1] = bk;
            }
        }
        __syncthreads();

        // ---- pass C: correction + scale + store (x from smem) ----
#pragma unroll
        for (int j = 0; j < TILE; ++j) {
            const int jr = tt * TILE + j;
            if (jr < nr) {
                const float4 xa = *reinterpret_cast<const float4*>(xs + j * NCOLS + colA);
                const float4 xb = *reinterpret_cast<const float4*>(xs + j * NCOLS + colB);
                ull a01 = pack2(xa.x, xa.y), a23 = pack2(xa.z, xa.w);
                ull a45 = pack2(xb.x, xb.y), a67 = pack2(xb.z, xb.w);
#pragma unroll
                for (int k = 0; k < 8; ++k) {
                    const ull bk = *reinterpret_cast<const ull*>(&B2[(j * 8 + k) * 2]);
                    a01 = ffma2(bk, VA0[k], a01);   // Tneg carries the minus
                    a23 = ffma2(bk, VA1[k], a23);
                    a45 = ffma2(bk, VB0[k], a45);
                    a67 = ffma2(bk, VB1[k], a67);
                }
                a01 = ffma2(a01, dA0, bA0);
                a23 = ffma2(a23, dA1, bA1);
                a45 = ffma2(a45, dB0, bB0);
                a67 = ffma2(a67, dB1, bB1);
                const float2 o0 = unpack2(a01), o1 = unpack2(a23);
                const float2 o2 = unpack2(a45), o3 = unpack2(a67);
                __stcs(reinterpret_cast<float4*>(y + (size_t)(r0 + jr) * NCOLS + colA),
                       make_float4(o0.x, o0.y, o1.x, o1.y));
                __stcs(reinterpret_cast<float4*>(y + (size_t)(r0 + jr) * NCOLS + colB),
                       make_float4(o2.x, o2.y, o3.x, o3.y));
            }
        }
    }
}

extern "C" void kernel_launch(void* const* d_in, const int* in_sizes, int n_in,
                              void* d_out, int out_size) {
    const float* x    = (const float*)d_in[0];
    const float* v    = (const float*)d_in[1];
    const float* dvec = (const float*)d_in[2];
    const float* bias = (const float*)d_in[3];
    float* y = (float*)d_out;
    (void)in_sizes; (void)n_in; (void)out_size;

    const int dyn = 2 * TILE * NCOLS * (int)sizeof(float);   // 98304 B
    static int attr_set = 0;
    if (!attr_set) {
        cudaFuncSetAttribute(orth_pipe,
                             cudaFuncAttributeMaxDynamicSharedMemorySize, dyn);
        attr_set = 1;
    }
    orth_pipe<<<NB, TPB, dyn>>>(x, v, dvec, bias, y);
}

// round 14
// speedup vs baseline: 1.0006x; 1.0006x over previous
#include <cuda_runtime.h>
#include <cstdint>

#define NCOLS 2048
#define ORDER 8
#define NB    148
#define TPB   512
#define TILE  8
#define NT    7

typedef unsigned long long ull;

__device__ __forceinline__ ull pack2(float lo, float hi) {
    ull r; asm("mov.b64 %0, {%1, %2};" : "=l"(r) : "f"(lo), "f"(hi)); return r;
}
__device__ __forceinline__ float2 unpack2(ull v) {
    float2 f; asm("mov.b64 {%0, %1}, %2;" : "=f"(f.x), "=f"(f.y) : "l"(v)); return f;
}
__device__ __forceinline__ ull ffma2(ull a, ull b, ull c) {
    ull d; asm("fma.rn.f32x2 %0, %1, %2, %3;" : "=l"(d) : "l"(a), "l"(b), "l"(c)); return d;
}
__device__ __forceinline__ ull fmul2(ull a, ull b) {
    ull d; asm("mul.rn.f32x2 %0, %1, %2;" : "=l"(d) : "l"(a), "l"(b)); return d;
}
__device__ __forceinline__ uint32_t s2u(const void* p) {
    uint32_t a;
    asm("{ .reg .u64 t; cvta.to.shared.u64 t, %1; cvt.u32.u64 %0, t; }"
        : "=r"(a) : "l"(p));
    return a;
}
__device__ __forceinline__ void cp16(uint32_t dst, const float* src) {
    asm volatile("cp.async.cg.shared.global [%0], [%1], 16;" :: "r"(dst), "l"(src));
}
__device__ __forceinline__ void cp_commit() { asm volatile("cp.async.commit_group;"); }
__device__ __forceinline__ void cp_wait1()  { asm volatile("cp.async.wait_group 1;"); }

// dynamic smem: xbuf[3][TILE][NCOLS] = 196608 bytes (triple-buffer ring)
extern __shared__ float xbuf[];

__global__ void __launch_bounds__(TPB, 1) orth_pipe(
    const float* __restrict__ x, const float* __restrict__ v,
    const float* __restrict__ d, const float* __restrict__ bias,
    float* __restrict__ y)
{
    __shared__ float gpart[16 * 36];
    __shared__ float Tneg[64];
    __shared__ float asum[16 * 65];          // stride 65: conflict-free collapse
    __shared__ float A2[2][TILE * 8 * 2];    // parity-buffered duplicated (a,a)

    const int t = threadIdx.x, lane = t & 31, w = t >> 5;
    const int c0 = t * 4;

    const int bid = blockIdx.x;
    const int nr = (bid < 52) ? 56 : 55;
    const int r0 = (bid < 52) ? bid * 56 : 52 * 56 + (bid - 52) * 55;

    // ---- prefetch tile 0 into ring slot 0 immediately ----
    const uint32_t xb_base = s2u(xbuf);
#pragma unroll
    for (int j = 0; j < TILE; ++j) {
        const int rc = (j < nr) ? j : (nr - 1);
        cp16(xb_base + (uint32_t)(j * NCOLS + c0) * 4,
             x + (size_t)(r0 + rc) * NCOLS + c0);
    }
    cp_commit();

    // ---- V slice ----
    float4 Vf[ORDER];
#pragma unroll
    for (int k = 0; k < ORDER; ++k)
        Vf[k] = *reinterpret_cast<const float4*>(v + k * NCOLS + c0);

    // ================= Prologue: Gram -> Tneg =================
    {
        int idx = 0;
#pragma unroll
        for (int i = 0; i < ORDER; ++i) {
#pragma unroll
            for (int k = i; k < ORDER; ++k) {
                float gg = Vf[i].x * Vf[k].x;
                gg = fmaf(Vf[i].y, Vf[k].y, gg);
                gg = fmaf(Vf[i].z, Vf[k].z, gg);
                gg = fmaf(Vf[i].w, Vf[k].w, gg);
#pragma unroll
                for (int m = 16; m >= 1; m >>= 1)
                    gg += __shfl_xor_sync(0xffffffffu, gg, m);
                if (lane == 0) gpart[w * 36 + idx] = gg;
                ++idx;
            }
        }
    }
    __syncthreads();
    if (t < 36) {
        float s = 0.f;
#pragma unroll
        for (int ww = 0; ww < 16; ++ww) s += gpart[ww * 36 + t];
        gpart[t] = s;
    }
    __syncthreads();
    if (t == 0) {
        float Gs[ORDER][ORDER];
        int id2 = 0;
        for (int i = 0; i < ORDER; ++i)
            for (int k = i; k < ORDER; ++k) {
                Gs[i][k] = gpart[id2]; Gs[k][i] = gpart[id2]; ++id2;
            }
        float rn[ORDER];
        for (int i = 0; i < ORDER; ++i) rn[i] = 1.0f / sqrtf(Gs[i][i]);
        float T[ORDER][ORDER];
        for (int i = 0; i < ORDER; ++i)
            for (int k = 0; k < ORDER; ++k) T[i][k] = 0.f;
        for (int i = 0; i < ORDER; ++i) T[i][i] = 2.f;
        for (int c = 1; c < ORDER; ++c)
            for (int r = 0; r < c; ++r) {
                float s = 0.f;
                for (int m = r; m < c; ++m)
                    s += T[r][m] * (Gs[m][c] * rn[m] * rn[c]);
                T[r][c] = -2.f * s;
            }
        for (int i = 0; i < ORDER; ++i)
            for (int k = 0; k < ORDER; ++k)
                Tneg[i * 8 + k] = -(rn[i] * T[i][k] * rn[k]);
    }
    __syncthreads();

    // ---- W = Tneg * V (correction vectors) + packed V for dots ----
    ull V0[ORDER], V1[ORDER], W0[ORDER], W1[ORDER];
#pragma unroll
    for (int i = 0; i < ORDER; ++i) {
        float4 acc = make_float4(0.f, 0.f, 0.f, 0.f);
#pragma unroll
        for (int k = 0; k < ORDER; ++k) {
            const float tk = Tneg[i * 8 + k];
            acc.x = fmaf(tk, Vf[k].x, acc.x);
            acc.y = fmaf(tk, Vf[k].y, acc.y);
            acc.z = fmaf(tk, Vf[k].z, acc.z);
            acc.w = fmaf(tk, Vf[k].w, acc.w);
        }
        W0[i] = pack2(acc.x, acc.y);
        W1[i] = pack2(acc.z, acc.w);
        V0[i] = pack2(Vf[i].x, Vf[i].y);
        V1[i] = pack2(Vf[i].z, Vf[i].w);
    }

    const float4 dv = *reinterpret_cast<const float4*>(d + c0);
    const float4 bv = *reinterpret_cast<const float4*>(bias + c0);
    const ull d01 = pack2(dv.x, dv.y), d23 = pack2(dv.z, dv.w);
    const ull b01 = pack2(bv.x, bv.y), b23 = pack2(bv.z, bv.w);

    float* yp = y + c0;

    // ================= Software-pipelined main loop =================
    // iter tt: [issue cp(tt+1)] [wait cp(tt)] [bar]
    //          phase1: passA(tt) + passC(tt-1)   [bar]
    //          phase2: passB(tt)
#pragma unroll 1
    for (int tt = 0; tt < NT; ++tt) {
        // issue prefetch of tile tt+1 into ring slot (tt+1)%3
        if (tt + 1 < NT) {
            const int slot = (tt + 1) % 3;
#pragma unroll
            for (int j = 0; j < TILE; ++j) {
                const int jr = (tt + 1) * TILE + j;
                const int rc = (jr < nr) ? jr : (nr - 1);
                cp16(xb_base + (uint32_t)((slot * TILE + j) * NCOLS + c0) * 4,
                     x + (size_t)(r0 + rc) * NCOLS + c0);
            }
        }
        cp_commit();            // commit (possibly empty) group
        cp_wait1();             // group tt complete; tt+1 may stay in flight
        __syncthreads();        // publishes tile tt + A2[(tt-1)&1] from passB

        const float* xs = &xbuf[(tt % 3) * TILE * NCOLS];

        // ---- phase 1a: pass A(tt): dots + folded butterfly -> asum ----
#pragma unroll
        for (int j = 0; j < TILE; ++j) {
            const float4 xv = *reinterpret_cast<const float4*>(xs + j * NCOLS + c0);
            const ull x01 = pack2(xv.x, xv.y);
            const ull x23 = pack2(xv.z, xv.w);
            float p[8];
#pragma unroll
            for (int k = 0; k < 8; ++k) {
                const float2 f = unpack2(ffma2(x23, V1[k], fmul2(x01, V0[k])));
                p[k] = f.x + f.y;
            }
#pragma unroll
            for (int k = 0; k < 8; ++k) {
                p[k] += __shfl_xor_sync(0xffffffffu, p[k], 16);
                p[k] += __shfl_xor_sync(0xffffffffu, p[k], 8);
            }
            const bool h4 = (lane & 4) != 0;
            float q[4];
#pragma unroll
            for (int jj = 0; jj < 4; ++jj) {
                float keep = h4 ? p[jj + 4] : p[jj];
                float send = h4 ? p[jj] : p[jj + 4];
                q[jj] = keep + __shfl_xor_sync(0xffffffffu, send, 4);
            }
            const bool h2 = (lane & 2) != 0;
            float r2[2];
#pragma unroll
            for (int jj = 0; jj < 2; ++jj) {
                float keep = h2 ? q[jj + 2] : q[jj];
                float send = h2 ? q[jj] : q[jj + 2];
                r2[jj] = keep + __shfl_xor_sync(0xffffffffu, send, 2);
            }
            const bool h1 = (lane & 1) != 0;
            float keep = h1 ? r2[1] : r2[0];
            float send = h1 ? r2[0] : r2[1];
            const float s = keep + __shfl_xor_sync(0xffffffffu, send, 1);
            if (lane < 8) asum[w * 65 + j * 8 + lane] = s;
        }

        // ---- phase 1b: pass C(tt-1): correction + scale + store ----
        if (tt > 0) {
            const float* xp = &xbuf[((tt - 1) % 3) * TILE * NCOLS];
            const float* A2p = A2[(tt - 1) & 1];
#pragma unroll
            for (int j = 0; j < TILE; ++j) {
                const int jr = (tt - 1) * TILE + j;
                if (jr < nr) {
                    const float4 xv = *reinterpret_cast<const float4*>(xp + j * NCOLS + c0);
                    ull a01 = pack2(xv.x, xv.y);
                    ull a23 = pack2(xv.z, xv.w);
#pragma unroll
                    for (int i = 0; i < 8; ++i) {
                        const ull aa = *reinterpret_cast<const ull*>(&A2p[(j * 8 + i) * 2]);
                        a01 = ffma2(aa, W0[i], a01);   // W carries Tneg's minus
                        a23 = ffma2(aa, W1[i], a23);
                    }
                    a01 = ffma2(a01, d01, b01);
                    a23 = ffma2(a23, d23, b23);
                    const float2 o0 = unpack2(a01), o1 = unpack2(a23);
                    __stcs(reinterpret_cast<float4*>(yp + (size_t)(r0 + jr) * NCOLS),
                           make_float4(o0.x, o0.y, o1.x, o1.y));
                }
            }
        }
        __syncthreads();

        // ---- phase 2: pass B(tt): collapse 16 warps -> A2[tt&1] ----
        if (t < TILE * 8) {
            float a = 0.f;
#pragma unroll
            for (int ww = 0; ww < 16; ++ww) a += asum[ww * 65 + t];
            A2[tt & 1][t * 2] = a;
            A2[tt & 1][t * 2 + 1] = a;
        }
    }

    // ================= Epilogue: pass C(NT-1) =================
    __syncthreads();
    {
        const float* xp = &xbuf[((NT - 1) % 3) * TILE * NCOLS];
        const float* A2p = A2[(NT - 1) & 1];
#pragma unroll
        for (int j = 0; j < TILE; ++j) {
            const int jr = (NT - 1) * TILE + j;
            if (jr < nr) {
                const float4 xv = *reinterpret_cast<const float4*>(xp + j * NCOLS + c0);
                ull a01 = pack2(xv.x, xv.y);
                ull a23 = pack2(xv.z, xv.w);
#pragma unroll
                for (int i = 0; i < 8; ++i) {
                    const ull aa = *reinterpret_cast<const ull*>(&A2p[(j * 8 + i) * 2]);
                    a01 = ffma2(aa, W0[i], a01);
                    a23 = ffma2(aa, W1[i], a23);
                }
                a01 = ffma2(a01, d01, b01);
                a23 = ffma2(a23, d23, b23);
                const float2 o0 = unpack2(a01), o1 = unpack2(a23);
                __stcs(reinterpret_cast<float4*>(yp + (size_t)(r0 + jr) * NCOLS),
                       make_float4(o0.x, o0.y, o1.x, o1.y));
            }
        }
    }
}

extern "C" void kernel_launch(void* const* d_in, const int* in_sizes, int n_in,
                              void* d_out, int out_size) {
    const float* x    = (const float*)d_in[0];
    const float* v    = (const float*)d_in[1];
    const float* dvec = (const float*)d_in[2];
    const float* bias = (const float*)d_in[3];
    float* y = (float*)d_out;
    (void)in_sizes; (void)n_in; (void)out_size;

    const int dyn = 3 * TILE * NCOLS * (int)sizeof(float);   // 196608 B
    static int attr_set = 0;
    if (!attr_set) {
        cudaFuncSetAttribute(orth_pipe,
                             cudaFuncAttributeMaxDynamicSharedMemorySize, dyn);
        attr_set = 1;
    }
    orth_pipe<<<NB, TPB, dyn>>>(x, v, dvec, bias, y);
}

// round 15
// speedup vs baseline: 1.0018x; 1.0012x over previous
#include <cuda_runtime.h>
#include <cstdint>

#define NCOLS 2048
#define ORDER 8
#define NB    148
#define TPB   512
#define TILE  12
#define NT    5

typedef unsigned long long ull;

__device__ __forceinline__ ull pack2(float lo, float hi) {
    ull r; asm("mov.b64 %0, {%1, %2};" : "=l"(r) : "f"(lo), "f"(hi)); return r;
}
__device__ __forceinline__ float2 unpack2(ull v) {
    float2 f; asm("mov.b64 {%0, %1}, %2;" : "=f"(f.x), "=f"(f.y) : "l"(v)); return f;
}
__device__ __forceinline__ ull ffma2(ull a, ull b, ull c) {
    ull d; asm("fma.rn.f32x2 %0, %1, %2, %3;" : "=l"(d) : "l"(a), "l"(b), "l"(c)); return d;
}
__device__ __forceinline__ ull fmul2(ull a, ull b) {
    ull d; asm("mul.rn.f32x2 %0, %1, %2;" : "=l"(d) : "l"(a), "l"(b)); return d;
}
__device__ __forceinline__ uint32_t s2u(const void* p) {
    uint32_t a;
    asm("{ .reg .u64 t; cvta.to.shared.u64 t, %1; cvt.u32.u64 %0, t; }"
        : "=r"(a) : "l"(p));
    return a;
}
__device__ __forceinline__ void cp16(uint32_t dst, const float* src) {
    asm volatile("cp.async.cg.shared.global [%0], [%1], 16;" :: "r"(dst), "l"(src));
}
__device__ __forceinline__ void cp_commit() { asm volatile("cp.async.commit_group;"); }
__device__ __forceinline__ void cp_wait0()  { asm volatile("cp.async.wait_group 0;"); }

// dynamic smem: xbuf[2][TILE][NCOLS] = 196608 bytes
extern __shared__ float xbuf[];

__global__ void __launch_bounds__(TPB, 1) orth_pipe(
    const float* __restrict__ x, const float* __restrict__ v,
    const float* __restrict__ d, const float* __restrict__ bias,
    float* __restrict__ y)
{
    __shared__ float gpart[16 * 36];
    __shared__ float Tneg[64];
    __shared__ float asum[16 * 97];        // [warp][row(12)*8+k], stride 97
    __shared__ float A2[TILE * 8 * 2];     // duplicated (a,a) pairs

    const int t = threadIdx.x, lane = t & 31, w = t >> 5;
    const int c0 = t * 4;

    const int bid = blockIdx.x;
    const int nr = (bid < 52) ? 56 : 55;
    const int r0 = (bid < 52) ? bid * 56 : 52 * 56 + (bid - 52) * 55;

    // ---- kick off prefetch of tile 0 immediately ----
    const uint32_t xb_base = s2u(xbuf);
#pragma unroll
    for (int j = 0; j < TILE; ++j) {
        const int rc = (j < nr) ? j : (nr - 1);
        cp16(xb_base + (uint32_t)(j * NCOLS + c0) * 4,
             x + (size_t)(r0 + rc) * NCOLS + c0);
    }
    cp_commit();

    // ---- V slice ----
    float4 Vf[ORDER];
#pragma unroll
    for (int k = 0; k < ORDER; ++k)
        Vf[k] = *reinterpret_cast<const float4*>(v + k * NCOLS + c0);

    // ================= Prologue: Gram -> Tneg =================
    {
        int idx = 0;
#pragma unroll
        for (int i = 0; i < ORDER; ++i) {
#pragma unroll
            for (int k = i; k < ORDER; ++k) {
                float gg = Vf[i].x * Vf[k].x;
                gg = fmaf(Vf[i].y, Vf[k].y, gg);
                gg = fmaf(Vf[i].z, Vf[k].z, gg);
                gg = fmaf(Vf[i].w, Vf[k].w, gg);
#pragma unroll
                for (int m = 16; m >= 1; m >>= 1)
                    gg += __shfl_xor_sync(0xffffffffu, gg, m);
                if (lane == 0) gpart[w * 36 + idx] = gg;
                ++idx;
            }
        }
    }
    __syncthreads();
    if (t < 36) {
        float s = 0.f;
#pragma unroll
        for (int ww = 0; ww < 16; ++ww) s += gpart[ww * 36 + t];
        gpart[t] = s;
    }
    __syncthreads();
    if (t == 0) {
        float Gs[ORDER][ORDER];
        int id2 = 0;
        for (int i = 0; i < ORDER; ++i)
            for (int k = i; k < ORDER; ++k) {
                Gs[i][k] = gpart[id2]; Gs[k][i] = gpart[id2]; ++id2;
            }
        float rn[ORDER];
        for (int i = 0; i < ORDER; ++i) rn[i] = 1.0f / sqrtf(Gs[i][i]);
        float T[ORDER][ORDER];
        for (int i = 0; i < ORDER; ++i)
            for (int k = 0; k < ORDER; ++k) T[i][k] = 0.f;
        for (int i = 0; i < ORDER; ++i) T[i][i] = 2.f;
        for (int c = 1; c < ORDER; ++c)
            for (int r = 0; r < c; ++r) {
                float s = 0.f;
                for (int m = r; m < c; ++m)
                    s += T[r][m] * (Gs[m][c] * rn[m] * rn[c]);
                T[r][c] = -2.f * s;
            }
        for (int i = 0; i < ORDER; ++i)
            for (int k = 0; k < ORDER; ++k)
                Tneg[i * 8 + k] = -(rn[i] * T[i][k] * rn[k]);
    }
    __syncthreads();

    // W = Tneg * V; keep BOTH V (dots) and W (correction), packed.
    ull V0[ORDER], V1[ORDER], W0[ORDER], W1[ORDER];
#pragma unroll
    for (int i = 0; i < ORDER; ++i) {
        float4 acc = make_float4(0.f, 0.f, 0.f, 0.f);
#pragma unroll
        for (int k = 0; k < ORDER; ++k) {
            const float tk = Tneg[i * 8 + k];
            acc.x = fmaf(tk, Vf[k].x, acc.x);
            acc.y = fmaf(tk, Vf[k].y, acc.y);
            acc.z = fmaf(tk, Vf[k].z, acc.z);
            acc.w = fmaf(tk, Vf[k].w, acc.w);
        }
        W0[i] = pack2(acc.x, acc.y);
        W1[i] = pack2(acc.z, acc.w);
        V0[i] = pack2(Vf[i].x, Vf[i].y);
        V1[i] = pack2(Vf[i].z, Vf[i].w);
    }

    const float4 dv = *reinterpret_cast<const float4*>(d + c0);
    const float4 bv = *reinterpret_cast<const float4*>(bias + c0);
    const ull d01 = pack2(dv.x, dv.y), d23 = pack2(dv.z, dv.w);
    const ull b01 = pack2(bv.x, bv.y), b23 = pack2(bv.z, bv.w);

    float* yp = y + c0;

    // ================= Pipelined main loop =================
#pragma unroll 1
    for (int tt = 0; tt < NT; ++tt) {
        const int buf = tt & 1;

        cp_wait0();
        __syncthreads();               // tile tt visible; prev pass C done

        // prefetch tile tt+1 into the other buffer
        if (tt + 1 < NT) {
#pragma unroll
            for (int j = 0; j < TILE; ++j) {
                const int jr = (tt + 1) * TILE + j;
                const int rc = (jr < nr) ? jr : (nr - 1);
                cp16(xb_base + (uint32_t)(((1 - buf) * TILE + j) * NCOLS + c0) * 4,
                     x + (size_t)(r0 + rc) * NCOLS + c0);
            }
            cp_commit();
        }

        const float* xs = &xbuf[buf * TILE * NCOLS];

        // ---- pass A: dots from smem + butterfly -> asum ----
#pragma unroll
        for (int j = 0; j < TILE; ++j) {
            const float4 xv = *reinterpret_cast<const float4*>(xs + j * NCOLS + c0);
            const ull x01 = pack2(xv.x, xv.y);
            const ull x23 = pack2(xv.z, xv.w);
            float p[8];
#pragma unroll
            for (int k = 0; k < 8; ++k) {
                const float2 f = unpack2(ffma2(x23, V1[k], fmul2(x01, V0[k])));
                p[k] = f.x + f.y;
            }
#pragma unroll
            for (int k = 0; k < 8; ++k) {
                p[k] += __shfl_xor_sync(0xffffffffu, p[k], 16);
                p[k] += __shfl_xor_sync(0xffffffffu, p[k], 8);
            }
            const bool h4 = (lane & 4) != 0;
            float q[4];
#pragma unroll
            for (int jj = 0; jj < 4; ++jj) {
                float keep = h4 ? p[jj + 4] : p[jj];
                float send = h4 ? p[jj] : p[jj + 4];
                q[jj] = keep + __shfl_xor_sync(0xffffffffu, send, 4);
            }
            const bool h2 = (lane & 2) != 0;
            float r2[2];
#pragma unroll
            for (int jj = 0; jj < 2; ++jj) {
                float keep = h2 ? q[jj + 2] : q[jj];
                float send = h2 ? q[jj] : q[jj + 2];
                r2[jj] = keep + __shfl_xor_sync(0xffffffffu, send, 2);
            }
            const bool h1 = (lane & 1) != 0;
            float keep = h1 ? r2[1] : r2[0];
            float send = h1 ? r2[0] : r2[1];
            const float s = keep + __shfl_xor_sync(0xffffffffu, send, 1);
            if (lane < 8) asum[w * 97 + j * 8 + lane] = s;
        }
        __syncthreads();

        // ---- pass B: collapse 16 warps (96 threads = 3 full warps) ----
        if (t < TILE * 8) {
            float a = 0.f;
#pragma unroll
            for (int ww = 0; ww < 16; ++ww) a += asum[ww * 97 + t];
            A2[t * 2] = a;
            A2[t * 2 + 1] = a;
        }
        __syncthreads();

        // ---- pass C: correction + scale + store (x from smem) ----
#pragma unroll
        for (int j = 0; j < TILE; ++j) {
            const int jr = tt * TILE + j;
            if (jr < nr) {
                const float4 xv = *reinterpret_cast<const float4*>(xs + j * NCOLS + c0);
                ull a01 = pack2(xv.x, xv.y);
                ull a23 = pack2(xv.z, xv.w);
#pragma unroll
                for (int i = 0; i < 8; ++i) {
                    const ull aa = *reinterpret_cast<const ull*>(&A2[(j * 8 + i) * 2]);
                    a01 = ffma2(aa, W0[i], a01);   // W carries Tneg's minus
                    a23 = ffma2(aa, W1[i], a23);
                }
                a01 = ffma2(a01, d01, b01);
                a23 = ffma2(a23, d23, b23);
                const float2 o0 = unpack2(a01), o1 = unpack2(a23);
                __stcs(reinterpret_cast<float4*>(yp + (size_t)(r0 + jr) * NCOLS),
                       make_float4(o0.x, o0.y, o1.x, o1.y));
            }
        }
    }
}

extern "C" void kernel_launch(void* const* d_in, const int* in_sizes, int n_in,
                              void* d_out, int out_size) {
    const float* x    = (const float*)d_in[0];
    const float* v    = (const float*)d_in[1];
    const float* dvec = (const float*)d_in[2];
    const float* bias = (const float*)d_in[3];
    float* y = (float*)d_out;
    (void)in_sizes; (void)n_in; (void)out_size;

    const int dyn = 2 * TILE * NCOLS * (int)sizeof(float);   // 196608 B
    static int attr_set = 0;
    if (!attr_set) {
        cudaFuncSetAttribute(orth_pipe,
                             cudaFuncAttributeMaxDynamicSharedMemorySize, dyn);
        attr_set = 1;
    }
    orth_pipe<<<NB, TPB, dyn>>>(x, v, dvec, bias, y);
}

// round 16
// speedup vs baseline: 1.2883x; 1.2860x over previous
#include <cuda_runtime.h>
#include <cstdint>

#define NCOLS 2048
#define ORDER 8
#define NB    148
#define TPB   512
#define TILE  8
#define NT    7

typedef unsigned long long ull;

__device__ __forceinline__ ull pack2(float lo, float hi) {
    ull r; asm("mov.b64 %0, {%1, %2};" : "=l"(r) : "f"(lo), "f"(hi)); return r;
}
__device__ __forceinline__ float2 unpack2(ull v) {
    float2 f; asm("mov.b64 {%0, %1}, %2;" : "=f"(f.x), "=f"(f.y) : "l"(v)); return f;
}
__device__ __forceinline__ ull ffma2(ull a, ull b, ull c) {
    ull d; asm("fma.rn.f32x2 %0, %1, %2, %3;" : "=l"(d) : "l"(a), "l"(b), "l"(c)); return d;
}
__device__ __forceinline__ ull fmul2(ull a, ull b) {
    ull d; asm("mul.rn.f32x2 %0, %1, %2;" : "=l"(d) : "l"(a), "l"(b)); return d;
}
__device__ __forceinline__ uint32_t s2u(const void* p) {
    uint32_t a;
    asm("{ .reg .u64 t; cvta.to.shared.u64 t, %1; cvt.u32.u64 %0, t; }"
        : "=r"(a) : "l"(p));
    return a;
}
__device__ __forceinline__ void cp16(uint32_t dst, const float* src) {
    asm volatile("cp.async.cg.shared.global [%0], [%1], 16;" :: "r"(dst), "l"(src));
}
__device__ __forceinline__ void cp_commit() { asm volatile("cp.async.commit_group;"); }
__device__ __forceinline__ void cp_wait0()  { asm volatile("cp.async.wait_group 0;"); }

// dynamic smem: xbuf[2][TILE][NCOLS] = 131072 bytes
extern __shared__ float xbuf[];

__global__ void __launch_bounds__(TPB, 1) orth_pipe(
    const float* __restrict__ x, const float* __restrict__ v,
    const float* __restrict__ d, const float* __restrict__ bias,
    float* __restrict__ y)
{
    __shared__ float gpart[16 * 36];
    __shared__ float Tneg[64];
    __shared__ float asum[16 * 65];        // stride 65 -> conflict-free collapse
    __shared__ float A2[TILE * 8 * 2];     // duplicated (A,A) pairs

    const int t = threadIdx.x, lane = t & 31, w = t >> 5;
    const int c0 = t * 4;

    const int bid = blockIdx.x;
    const int nr = (bid < 52) ? 56 : 55;
    const int r0 = (bid < 52) ? bid * 56 : 52 * 56 + (bid - 52) * 55;

    // ---- kick off prefetch of tile 0 immediately ----
    const uint32_t xb_base = s2u(xbuf);
#pragma unroll
    for (int j = 0; j < TILE; ++j) {
        const int rc = (j < nr) ? j : (nr - 1);
        cp16(xb_base + (uint32_t)((0 * TILE + j) * NCOLS + c0) * 4,
             x + (size_t)(r0 + rc) * NCOLS + c0);
    }
    cp_commit();

    // ---- V slice ----
    float4 Vf[ORDER];
#pragma unroll
    for (int k = 0; k < ORDER; ++k)
        Vf[k] = *reinterpret_cast<const float4*>(v + k * NCOLS + c0);

    // ================= Prologue: Gram -> Tneg =================
    {
        int idx = 0;
#pragma unroll
        for (int i = 0; i < ORDER; ++i) {
#pragma unroll
            for (int k = i; k < ORDER; ++k) {
                float gg = Vf[i].x * Vf[k].x;
                gg = fmaf(Vf[i].y, Vf[k].y, gg);
                gg = fmaf(Vf[i].z, Vf[k].z, gg);
                gg = fmaf(Vf[i].w, Vf[k].w, gg);
#pragma unroll
                for (int m = 16; m >= 1; m >>= 1)
                    gg += __shfl_xor_sync(0xffffffffu, gg, m);
                if (lane == 0) gpart[w * 36 + idx] = gg;
                ++idx;
            }
        }
    }
    __syncthreads();
    if (t < 36) {
        float s = 0.f;
#pragma unroll
        for (int ww = 0; ww < 16; ++ww) s += gpart[ww * 36 + t];
        gpart[t] = s;
    }
    __syncthreads();
    if (t == 0) {
        float Gs[ORDER][ORDER];
        int id2 = 0;
        for (int i = 0; i < ORDER; ++i)
            for (int k = i; k < ORDER; ++k) {
                Gs[i][k] = gpart[id2]; Gs[k][i] = gpart[id2]; ++id2;
            }
        float rn[ORDER];
        for (int i = 0; i < ORDER; ++i) rn[i] = 1.0f / sqrtf(Gs[i][i]);
        float T[ORDER][ORDER];
        for (int i = 0; i < ORDER; ++i)
            for (int k = 0; k < ORDER; ++k) T[i][k] = 0.f;
        for (int i = 0; i < ORDER; ++i) T[i][i] = 2.f;
        for (int c = 1; c < ORDER; ++c)
            for (int r = 0; r < c; ++r) {
                float s = 0.f;
                for (int m = r; m < c; ++m)
                    s += T[r][m] * (Gs[m][c] * rn[m] * rn[c]);
                T[r][c] = -2.f * s;
            }
        for (int i = 0; i < ORDER; ++i)
            for (int k = 0; k < ORDER; ++k)
                Tneg[i * 8 + k] = -(rn[i] * T[i][k] * rn[k]);
    }
    __syncthreads();

    // W = Tneg * V; keep BOTH V (dots) and W (correction), packed.
    ull V0[ORDER], V1[ORDER], W0[ORDER], W1[ORDER];
#pragma unroll
    for (int i = 0; i < ORDER; ++i) {
        float4 acc = make_float4(0.f, 0.f, 0.f, 0.f);
#pragma unroll
        for (int k = 0; k < ORDER; ++k) {
            const float tk = Tneg[i * 8 + k];
            acc.x = fmaf(tk, Vf[k].x, acc.x);
            acc.y = fmaf(tk, Vf[k].y, acc.y);
            acc.z = fmaf(tk, Vf[k].z, acc.z);
            acc.w = fmaf(tk, Vf[k].w, acc.w);
        }
        W0[i] = pack2(acc.x, acc.y);
        W1[i] = pack2(acc.z, acc.w);
        V0[i] = pack2(Vf[i].x, Vf[i].y);
        V1[i] = pack2(Vf[i].z, Vf[i].w);
    }

    const float4 dv = *reinterpret_cast<const float4*>(d + c0);
    const float4 bv = *reinterpret_cast<const float4*>(bias + c0);
    const ull d01 = pack2(dv.x, dv.y), d23 = pack2(dv.z, dv.w);
    const ull b01 = pack2(bv.x, bv.y), b23 = pack2(bv.z, bv.w);

    float* yp = y + c0;

    // ================= Pipelined main loop =================
#pragma unroll 1
    for (int tt = 0; tt < NT; ++tt) {
        const int buf = tt & 1;

        cp_wait0();
        __syncthreads();               // tile tt visible; prev pass C done

        // prefetch tile tt+1 into the other buffer
        if (tt + 1 < NT) {
#pragma unroll
            for (int j = 0; j < TILE; ++j) {
                const int jr = (tt + 1) * TILE + j;
                const int rc = (jr < nr) ? jr : (nr - 1);
                cp16(xb_base + (uint32_t)(((1 - buf) * TILE + j) * NCOLS + c0) * 4,
                     x + (size_t)(r0 + rc) * NCOLS + c0);
            }
            cp_commit();
        }

        const float* xs = &xbuf[buf * TILE * NCOLS];

        // ---- pass A: dots from smem + butterfly -> asum ----
#pragma unroll
        for (int j = 0; j < TILE; ++j) {
            const float4 xv = *reinterpret_cast<const float4*>(xs + j * NCOLS + c0);
            const ull x01 = pack2(xv.x, xv.y);
            const ull x23 = pack2(xv.z, xv.w);
            float p[8];
#pragma unroll
            for (int k = 0; k < 8; ++k) {
                const float2 f = unpack2(ffma2(x23, V1[k], fmul2(x01, V0[k])));
                p[k] = f.x + f.y;
            }
#pragma unroll
            for (int k = 0; k < 8; ++k) {
                p[k] += __shfl_xor_sync(0xffffffffu, p[k], 16);
                p[k] += __shfl_xor_sync(0xffffffffu, p[k], 8);
            }
            const bool h4 = (lane & 4) != 0;
            float q[4];
#pragma unroll
            for (int jj = 0; jj < 4; ++jj) {
                float keep = h4 ? p[jj + 4] : p[jj];
                float send = h4 ? p[jj] : p[jj + 4];
                q[jj] = keep + __shfl_xor_sync(0xffffffffu, send, 4);
            }
            const bool h2 = (lane & 2) != 0;
            float r2[2];
#pragma unroll
            for (int jj = 0; jj < 2; ++jj) {
                float keep = h2 ? q[jj + 2] : q[jj];
                float send = h2 ? q[jj] : q[jj + 2];
                r2[jj] = keep + __shfl_xor_sync(0xffffffffu, send, 2);
            }
            const bool h1 = (lane & 1) != 0;
            float keep = h1 ? r2[1] : r2[0];
            float send = h1 ? r2[0] : r2[1];
            const float s = keep + __shfl_xor_sync(0xffffffffu, send, 1);
            if (lane < 8) asum[w * 65 + j * 8 + lane] = s;
        }
        __syncthreads();

        // ---- pass B: collapse 16 warps with 128 threads ----
        // lane pair (2i, 2i+1) handles (row,k)=i: each sums 8 warp-partials,
        // shfl_xor(1) combines, even lane stores the duplicated pair.
        if (t < TILE * 8 * 2) {
            const int idx = t >> 1;            // (row*8+k)
            const int half = t & 1;            // which 8 warps
            float a = 0.f;
#pragma unroll
            for (int ww = 0; ww < 8; ++ww)
                a += asum[(half * 8 + ww) * 65 + idx];
            a += __shfl_xor_sync(0xffffffffu, a, 1);
            if (half == 0) {
                A2[idx * 2] = a;
                A2[idx * 2 + 1] = a;
            }
        }
        __syncthreads();

        // ---- pass C: correction + scale + store (x from smem) ----
#pragma unroll
        for (int j = 0; j < TILE; ++j) {
            const int jr = tt * TILE + j;
            if (jr < nr) {
                const float4 xv = *reinterpret_cast<const float4*>(xs + j * NCOLS + c0);
                ull a01 = pack2(xv.x, xv.y);
                ull a23 = pack2(xv.z, xv.w);
#pragma unroll
                for (int i = 0; i < 8; ++i) {
                    const ull aa = *reinterpret_cast<const ull*>(&A2[(j * 8 + i) * 2]);
                    a01 = ffma2(aa, W0[i], a01);   // W carries Tneg's minus
                    a23 = ffma2(aa, W1[i], a23);
                }
                a01 = ffma2(a01, d01, b01);
                a23 = ffma2(a23, d23, b23);
                const float2 o0 = unpack2(a01), o1 = unpack2(a23);
                __stcs(reinterpret_cast<float4*>(yp + (size_t)(r0 + jr) * NCOLS),
                       make_float4(o0.x, o0.y, o1.x, o1.y));
            }
        }
    }
}

extern "C" void kernel_launch(void* const* d_in, const int* in_sizes, int n_in,
                              void* d_out, int out_size) {
    const float* x    = (const float*)d_in[0];
    const float* v    = (const float*)d_in[1];
    const float* dvec = (const float*)d_in[2];
    const float* bias = (const float*)d_in[3];
    float* y = (float*)d_out;
    (void)in_sizes; (void)n_in; (void)out_size;

    const int dyn = 2 * TILE * NCOLS * (int)sizeof(float);   // 131072 B
    static int attr_set = 0;
    if (!attr_set) {
        cudaFuncSetAttribute(orth_pipe,
                             cudaFuncAttributeMaxDynamicSharedMemorySize, dyn);
        attr_set = 1;
    }
    orth_pipe<<<NB, TPB, dyn>>>(x, v, dvec, bias, y);
}